// round 1
// baseline (speedup 1.0000x reference)
#include <cuda_runtime.h>
#include <math.h>

#define N_NODES 20000
#define N_EDGES 320000
#define HDIM    256
#define EDIM    64
#define S_STEPS 4

// ---------------- device-global scratch (no runtime allocation) -------------
__device__ float g_Y [N_NODES * 512];          // [hn | agg]   per node
__device__ float g_AB[N_NODES * 512];          // [A   | B ]   per node
__device__ float g_C [N_EDGES * 256];          // ea @ W1c + b1 per edge
__device__ float g_P [N_NODES * 256];          // segsum(silu(hidden))
__device__ float g_G [N_NODES * 256];          // P @ eW2
__device__ float g_T [N_NODES * 512];          // silu(y@nW1+nb1)
__device__ float g_deg[N_NODES];
__device__ int   g_src[N_EDGES];
__device__ int   g_dst[N_EDGES];
__device__ int   g_is64;

__device__ __forceinline__ float silu_f(float v) { return v / (1.0f + expf(-v)); }

// ---------------- index dtype detection + conversion ------------------------
__global__ void detect_idx_kernel(const long long* __restrict__ p) {
    __shared__ int bad;
    if (threadIdx.x == 0) bad = 0;
    __syncthreads();
    long long v = p[threadIdx.x];          // first 64 int64 values
    if (v < 0 || v >= N_NODES) bad = 1;    // benign race
    __syncthreads();
    if (threadIdx.x == 0) g_is64 = bad ? 0 : 1;
}

__global__ void convert_idx_kernel(const void* __restrict__ ei) {
    int e = blockIdx.x * blockDim.x + threadIdx.x;
    if (e >= N_EDGES) return;
    int s, d;
    if (g_is64) {
        const long long* p = (const long long*)ei;
        s = (int)p[e]; d = (int)p[N_EDGES + e];
    } else {
        const int* p = (const int*)ei;
        s = p[e]; d = p[N_EDGES + e];
    }
    g_src[e] = s; g_dst[e] = d;
    atomicAdd(&g_deg[d], 1.0f);
}

// ---------------- layer norm (optionally with 1/deg scale + pre-bias) -------
__global__ void ln_kernel(const float* __restrict__ x, long ldx,
                          const float* __restrict__ gamma,
                          const float* __restrict__ beta,
                          const float* __restrict__ preBias,   // may be null
                          const float* __restrict__ deg,       // may be null
                          float* __restrict__ out, long ldo) {
    int n = blockIdx.x, t = threadIdx.x;     // 256 threads, HDIM elems
    float v = x[(long)n * ldx + t];
    if (deg) v = v / fmaxf(deg[n], 1.0f) + preBias[t];
    float s = v, s2 = v * v;
    #pragma unroll
    for (int o = 16; o; o >>= 1) {
        s  += __shfl_xor_sync(0xFFFFFFFFu, s,  o);
        s2 += __shfl_xor_sync(0xFFFFFFFFu, s2, o);
    }
    __shared__ float as[8], as2[8];
    int w = t >> 5, l = t & 31;
    if (l == 0) { as[w] = s; as2[w] = s2; }
    __syncthreads();
    float S = 0.f, S2 = 0.f;
    #pragma unroll
    for (int i = 0; i < 8; i++) { S += as[i]; S2 += as2[i]; }
    float mean = S * (1.0f / 256.0f);
    float var  = S2 * (1.0f / 256.0f) - mean * mean;
    float rstd = rsqrtf(var + 1e-5f);
    out[(long)n * ldo + t] = (v - mean) * rstd * gamma[t] + beta[t];
}

// ---------------- generic tiled SGEMM: Out = op(A@W + bias) ------------------
// BM=BN=64, BK=16, 256 threads, 4x4 microtile.
// act: 0 none, 1 silu.  accum: 0 store, 1 add-into-Out.
__global__ void sgemm_kernel(const float* __restrict__ A, long lda,
                             const float* __restrict__ W, long ldw,
                             const float* __restrict__ bias,
                             float* __restrict__ Out, long ldo,
                             int M, int K, int Nc, int act, int accum) {
    __shared__ float As[16][64];
    __shared__ float Ws[16][64];
    const int bm = blockIdx.y * 64;
    const int bn = blockIdx.x * 64;
    const int tid = threadIdx.x;
    const int tr = tid >> 4;            // 0..15
    const int tc = tid & 15;            // 0..15

    float acc[4][4];
    #pragma unroll
    for (int i = 0; i < 4; i++)
        #pragma unroll
        for (int j = 0; j < 4; j++) acc[i][j] = 0.0f;

    const int am = tid >> 2;            // 0..63
    const int ak = (tid & 3) << 2;      // 0,4,8,12
    const int wk = tid >> 4;            // 0..15
    const int wn = (tid & 15) << 2;     // 0..60

    for (int k0 = 0; k0 < K; k0 += 16) {
        float4 av = make_float4(0.f, 0.f, 0.f, 0.f);
        int arow = bm + am;
        if (arow < M) av = *(const float4*)&A[(long)arow * lda + k0 + ak];
        As[ak + 0][am] = av.x; As[ak + 1][am] = av.y;
        As[ak + 2][am] = av.z; As[ak + 3][am] = av.w;
        float4 wv = *(const float4*)&W[(long)(k0 + wk) * ldw + bn + wn];
        *(float4*)&Ws[wk][wn] = wv;
        __syncthreads();
        #pragma unroll
        for (int kk = 0; kk < 16; kk++) {
            float4 a4 = *(const float4*)&As[kk][tr << 2];
            float4 b4 = *(const float4*)&Ws[kk][tc << 2];
            float a[4] = {a4.x, a4.y, a4.z, a4.w};
            float b[4] = {b4.x, b4.y, b4.z, b4.w};
            #pragma unroll
            for (int i = 0; i < 4; i++)
                #pragma unroll
                for (int j = 0; j < 4; j++)
                    acc[i][j] += a[i] * b[j];
        }
        __syncthreads();
    }

    #pragma unroll
    for (int i = 0; i < 4; i++) {
        int m = bm + (tr << 2) + i;
        if (m >= M) continue;
        #pragma unroll
        for (int j = 0; j < 4; j++) {
            int n = bn + (tc << 2) + j;
            float v = acc[i][j];
            if (bias) v += bias[n];
            if (act)  v = silu_f(v);
            long off = (long)m * ldo + n;
            if (accum) Out[off] += v;
            else       Out[off] = v;
        }
    }
}

// ---------------- edge combine: silu(A[src]+B[dst]+C[e]) scatter into P -----
__global__ void edge_combine_kernel() {
    long idx = (long)blockIdx.x * blockDim.x + threadIdx.x;  // E * 64 items
    if (idx >= (long)N_EDGES * 64) return;
    int e  = (int)(idx >> 6);
    int j  = ((int)idx & 63) << 2;   // float4 offset within 256
    int s  = g_src[e];
    int d  = g_dst[e];
    float4 a = *(const float4*)&g_AB[(long)s * 512 + j];
    float4 b = *(const float4*)&g_AB[(long)d * 512 + 256 + j];
    float4 c = *(const float4*)&g_C[(long)e * 256 + j];
    float r0 = silu_f(a.x + b.x + c.x);
    float r1 = silu_f(a.y + b.y + c.y);
    float r2 = silu_f(a.z + b.z + c.z);
    float r3 = silu_f(a.w + b.w + c.w);
    float* p = &g_P[(long)d * 256 + j];
    atomicAdd(p + 0, r0);
    atomicAdd(p + 1, r1);
    atomicAdd(p + 2, r2);
    atomicAdd(p + 3, r3);
}

// ---------------- launch ------------------------------------------------------
extern "C" void kernel_launch(void* const* d_in, const int* in_sizes, int n_in,
                              void* d_out, int out_size) {
    const float* node_state = (const float*)d_in[0];
    const float* nn_g = (const float*)d_in[2];
    const float* nn_b = (const float*)d_in[3];
    const float* mn_g = (const float*)d_in[4];
    const float* mn_b = (const float*)d_in[5];
    const float* eW1  = (const float*)d_in[6];
    const float* eb1  = (const float*)d_in[7];
    const float* eW2  = (const float*)d_in[8];
    const float* eb2  = (const float*)d_in[9];
    const float* nW1  = (const float*)d_in[10];
    const float* nb1  = (const float*)d_in[11];
    const float* nW2  = (const float*)d_in[12];
    const float* nb2  = (const float*)d_in[13];
    const void*  eidx = d_in[14];
    const float* edge_attr = (const float*)d_in[1];
    float* h = (float*)d_out;

    void *pY, *pAB, *pC, *pP, *pG, *pT, *pdeg;
    cudaGetSymbolAddress(&pY,  g_Y);
    cudaGetSymbolAddress(&pAB, g_AB);
    cudaGetSymbolAddress(&pC,  g_C);
    cudaGetSymbolAddress(&pP,  g_P);
    cudaGetSymbolAddress(&pG,  g_G);
    cudaGetSymbolAddress(&pT,  g_T);
    cudaGetSymbolAddress(&pdeg, g_deg);

    float* fY  = (float*)pY;
    float* fAB = (float*)pAB;
    float* fC  = (float*)pC;
    float* fP  = (float*)pP;
    float* fG  = (float*)pG;
    float* fT  = (float*)pT;
    float* fdeg = (float*)pdeg;

    // h = node_state
    cudaMemcpyAsync(h, node_state, (size_t)N_NODES * HDIM * sizeof(float),
                    cudaMemcpyDeviceToDevice, 0);
    // degree (+ index conversion), computed once per launch
    cudaMemsetAsync(pdeg, 0, N_NODES * sizeof(float), 0);
    detect_idx_kernel<<<1, 64>>>((const long long*)eidx);
    convert_idx_kernel<<<(N_EDGES + 255) / 256, 256>>>(eidx);

    dim3 gN256(4, (N_NODES + 63) / 64);    // Nc=256 node GEMMs
    dim3 gN512(8, (N_NODES + 63) / 64);    // Nc=512 node GEMM
    dim3 gE256(4, N_EDGES / 64);           // edge-attr GEMM

    for (int i = 0; i < S_STEPS; i++) {
        const float* eW1i = eW1 + (long)i * 576 * 256;
        // 1. hn = LN(h) -> g_Y[:, 0:256]
        ln_kernel<<<N_NODES, 256>>>(h, 256, nn_g + i * HDIM, nn_b + i * HDIM,
                                    nullptr, nullptr, fY, 512);
        // 2. A = hn @ W1a -> g_AB[:,0:256];  B = hn @ W1b -> g_AB[:,256:512]
        sgemm_kernel<<<gN256, 256>>>(fY, 512, eW1i, 256, nullptr,
                                     fAB, 512, N_NODES, 256, 256, 0, 0);
        sgemm_kernel<<<gN256, 256>>>(fY, 512, eW1i + 256 * 256, 256, nullptr,
                                     fAB + 256, 512, N_NODES, 256, 256, 0, 0);
        // 3. C = ea @ W1c + eb1 -> g_C  [E,256]
        sgemm_kernel<<<gE256, 256>>>(edge_attr, 64, eW1i + 512 * 256, 256,
                                     eb1 + i * HDIM, fC, 256,
                                     N_EDGES, 64, 256, 0, 0);
        // 4. P = segsum_dst( silu(A[src]+B[dst]+C) )
        cudaMemsetAsync(pP, 0, (size_t)N_NODES * 256 * sizeof(float), 0);
        edge_combine_kernel<<<(N_EDGES * 64) / 256, 256>>>();
        // 5. G = P @ eW2
        sgemm_kernel<<<gN256, 256>>>(fP, 256, eW2 + (long)i * 256 * 256, 256,
                                     nullptr, fG, 256, N_NODES, 256, 256, 0, 0);
        // 6. agg = LN(G/deg + eb2) -> g_Y[:,256:512]
        ln_kernel<<<N_NODES, 256>>>(fG, 256, mn_g + i * HDIM, mn_b + i * HDIM,
                                    eb2 + i * HDIM, fdeg, fY + 256, 512);
        // 7. T = silu(y @ nW1 + nb1)
        sgemm_kernel<<<gN512, 256>>>(fY, 512, nW1 + (long)i * 512 * 512, 512,
                                     nb1 + i * 512, fT, 512,
                                     N_NODES, 512, 512, 1, 0);
        // 8. h += T @ nW2 + nb2
        sgemm_kernel<<<gN256, 256>>>(fT, 512, nW2 + (long)i * 512 * 256, 256,
                                     nb2 + i * HDIM, h, 256,
                                     N_NODES, 512, 256, 0, 1);
    }
}

// round 2
// speedup vs baseline: 1.2765x; 1.2765x over previous
#include <cuda_runtime.h>
#include <math.h>

#define N_NODES 20000
#define N_EDGES 320000
#define HDIM    256
#define EDIM    64
#define S_STEPS 4

// ---------------- device-global scratch (no runtime allocation) -------------
__device__ float g_Y [N_NODES * 512];          // [hn | agg]   per node
__device__ float g_AB[N_NODES * 512];          // [A   | B ]   per node
__device__ float g_C [N_EDGES * 256];          // ea @ W1c + b1 per edge
__device__ float g_P [N_NODES * 256];          // segsum(silu(hidden))
__device__ float g_G [N_NODES * 256];          // P @ eW2
__device__ float g_T [N_NODES * 512];          // silu(y@nW1+nb1)
__device__ float g_deg[N_NODES];
__device__ int   g_src[N_EDGES];
__device__ int   g_dst[N_EDGES];
__device__ int   g_is64;

__device__ __forceinline__ float silu_f(float v) {
    return __fdividef(v, 1.0f + __expf(-v));
}

// packed f32x2 helpers
__device__ __forceinline__ void fma2(unsigned long long& d,
                                     unsigned long long a,
                                     unsigned long long b) {
    asm("fma.rn.f32x2 %0, %1, %2, %0;" : "+l"(d) : "l"(a), "l"(b));
}
__device__ __forceinline__ unsigned long long dup2(float v) {
    unsigned long long r;
    asm("mov.b64 %0, {%1, %1};" : "=l"(r) : "f"(v));
    return r;
}

union F4U { float4 f; unsigned long long u[2]; };
union U2F { unsigned long long u; float2 f; };

// ---------------- index dtype detection + conversion ------------------------
__global__ void detect_idx_kernel(const long long* __restrict__ p) {
    __shared__ int bad;
    if (threadIdx.x == 0) bad = 0;
    __syncthreads();
    long long v = p[threadIdx.x];
    if (v < 0 || v >= N_NODES) bad = 1;
    __syncthreads();
    if (threadIdx.x == 0) g_is64 = bad ? 0 : 1;
}

__global__ void convert_idx_kernel(const void* __restrict__ ei) {
    int e = blockIdx.x * blockDim.x + threadIdx.x;
    if (e >= N_EDGES) return;
    int s, d;
    if (g_is64) {
        const long long* p = (const long long*)ei;
        s = (int)p[e]; d = (int)p[N_EDGES + e];
    } else {
        const int* p = (const int*)ei;
        s = p[e]; d = p[N_EDGES + e];
    }
    g_src[e] = s; g_dst[e] = d;
    atomicAdd(&g_deg[d], 1.0f);
}

// ---------------- layer norm ------------------------------------------------
__global__ void ln_kernel(const float* __restrict__ x, long ldx,
                          const float* __restrict__ gamma,
                          const float* __restrict__ beta,
                          const float* __restrict__ preBias,
                          const float* __restrict__ deg,
                          float* __restrict__ out, long ldo) {
    int n = blockIdx.x, t = threadIdx.x;
    float v = x[(long)n * ldx + t];
    if (deg) v = v / fmaxf(deg[n], 1.0f) + preBias[t];
    float s = v, s2 = v * v;
    #pragma unroll
    for (int o = 16; o; o >>= 1) {
        s  += __shfl_xor_sync(0xFFFFFFFFu, s,  o);
        s2 += __shfl_xor_sync(0xFFFFFFFFu, s2, o);
    }
    __shared__ float as[8], as2[8];
    int w = t >> 5, l = t & 31;
    if (l == 0) { as[w] = s; as2[w] = s2; }
    __syncthreads();
    float S = 0.f, S2 = 0.f;
    #pragma unroll
    for (int i = 0; i < 8; i++) { S += as[i]; S2 += as2[i]; }
    float mean = S * (1.0f / 256.0f);
    float var  = S2 * (1.0f / 256.0f) - mean * mean;
    float rstd = rsqrtf(var + 1e-5f);
    out[(long)n * ldo + t] = (v - mean) * rstd * gamma[t] + beta[t];
}

// ---------------- FFMA2 SGEMM: Out = op(A@W + bias) --------------------------
// BM=BN=128, BK=16, 256 threads, 8x8 microtile, f32x2 packed accumulators
// (paired along M), double-buffered smem. K must be a multiple of 16.
// act: 0 none, 1 silu.  accum: 0 store, 1 add-into-Out.
__global__ void __launch_bounds__(256, 2)
sgemm2_kernel(const float* __restrict__ A, long lda,
              const float* __restrict__ W, long ldw,
              const float* __restrict__ bias,
              float* __restrict__ Out, long ldo,
              int M, int K, int act, int accum) {
    __shared__ float As[2][16][128];
    __shared__ float Bs[2][16][128];
    const int bm  = blockIdx.y * 128;
    const int bn  = blockIdx.x * 128;
    const int tid = threadIdx.x;
    const int tm  = tid >> 4;            // 0..15
    const int tn  = tid & 15;            // 0..15

    // A loader: row = tid&127, k-half = (tid>>7)*8
    const int arow = tid & 127;
    const int akh  = (tid >> 7) * 8;
    const bool aok = (bm + arow) < M;
    // B loader: k-row = tid>>4, col quads at bnq and 64+bnq
    const int bkr = tid >> 4;
    const int bnq = (tid & 15) * 4;

    const int nk = K >> 4;

    unsigned long long acc[4][8];
    #pragma unroll
    for (int i = 0; i < 4; i++)
        #pragma unroll
        for (int j = 0; j < 8; j++) acc[i][j] = 0ull;

    float4 ra0, ra1, rb0, rb1;

    // prefetch tile 0
    {
        const float* Ap = A + (long)(bm + arow) * lda + akh;
        ra0 = aok ? *(const float4*)(Ap)     : make_float4(0,0,0,0);
        ra1 = aok ? *(const float4*)(Ap + 4) : make_float4(0,0,0,0);
        const float* Wp = W + (long)bkr * ldw + bn;
        rb0 = *(const float4*)(Wp + bnq);
        rb1 = *(const float4*)(Wp + 64 + bnq);
    }
    // store tile 0 -> buf 0
    As[0][akh + 0][arow] = ra0.x; As[0][akh + 1][arow] = ra0.y;
    As[0][akh + 2][arow] = ra0.z; As[0][akh + 3][arow] = ra0.w;
    As[0][akh + 4][arow] = ra1.x; As[0][akh + 5][arow] = ra1.y;
    As[0][akh + 6][arow] = ra1.z; As[0][akh + 7][arow] = ra1.w;
    *(float4*)&Bs[0][bkr][bnq]      = rb0;
    *(float4*)&Bs[0][bkr][64 + bnq] = rb1;
    __syncthreads();

    int buf = 0;
    for (int kt = 0; kt < nk; kt++) {
        const bool more = (kt + 1) < nk;
        if (more) {
            const int k0 = (kt + 1) << 4;
            const float* Ap = A + (long)(bm + arow) * lda + k0 + akh;
            ra0 = aok ? *(const float4*)(Ap)     : make_float4(0,0,0,0);
            ra1 = aok ? *(const float4*)(Ap + 4) : make_float4(0,0,0,0);
            const float* Wp = W + (long)(k0 + bkr) * ldw + bn;
            rb0 = *(const float4*)(Wp + bnq);
            rb1 = *(const float4*)(Wp + 64 + bnq);
        }
        #pragma unroll
        for (int kk = 0; kk < 16; kk++) {
            F4U a0, a1, b0, b1;
            a0.f = *(const float4*)&As[buf][kk][tm * 4];
            a1.f = *(const float4*)&As[buf][kk][64 + tm * 4];
            b0.f = *(const float4*)&Bs[buf][kk][tn * 4];
            b1.f = *(const float4*)&Bs[buf][kk][64 + tn * 4];
            unsigned long long aa[4] = { a0.u[0], a0.u[1], a1.u[0], a1.u[1] };
            unsigned long long bb[8] = {
                dup2(b0.f.x), dup2(b0.f.y), dup2(b0.f.z), dup2(b0.f.w),
                dup2(b1.f.x), dup2(b1.f.y), dup2(b1.f.z), dup2(b1.f.w) };
            #pragma unroll
            for (int i = 0; i < 4; i++)
                #pragma unroll
                for (int j = 0; j < 8; j++)
                    fma2(acc[i][j], aa[i], bb[j]);
        }
        if (more) {
            const int nb = buf ^ 1;
            As[nb][akh + 0][arow] = ra0.x; As[nb][akh + 1][arow] = ra0.y;
            As[nb][akh + 2][arow] = ra0.z; As[nb][akh + 3][arow] = ra0.w;
            As[nb][akh + 4][arow] = ra1.x; As[nb][akh + 5][arow] = ra1.y;
            As[nb][akh + 6][arow] = ra1.z; As[nb][akh + 7][arow] = ra1.w;
            *(float4*)&Bs[nb][bkr][bnq]      = rb0;
            *(float4*)&Bs[nb][bkr][64 + bnq] = rb1;
            __syncthreads();
        }
        buf ^= 1;
    }

    // epilogue
    float4 blo = make_float4(0,0,0,0), bhi = make_float4(0,0,0,0);
    if (bias) {
        blo = *(const float4*)&bias[bn + tn * 4];
        bhi = *(const float4*)&bias[bn + 64 + tn * 4];
    }
    const int nlo = bn + tn * 4;
    const int nhi = bn + 64 + tn * 4;
    #pragma unroll
    for (int rp = 0; rp < 4; rp++) {
        const int rbase = (rp < 2) ? (tm * 4 + rp * 2) : (64 + tm * 4 + (rp - 2) * 2);
        #pragma unroll
        for (int lane = 0; lane < 2; lane++) {
            const int m = bm + rbase + lane;
            if (m >= M) continue;
            float vl[4], vh[4];
            #pragma unroll
            for (int j = 0; j < 4; j++) {
                U2F t; t.u = acc[rp][j];     vl[j] = lane ? t.f.y : t.f.x;
                U2F s; s.u = acc[rp][4 + j]; vh[j] = lane ? s.f.y : s.f.x;
            }
            vl[0] += blo.x; vl[1] += blo.y; vl[2] += blo.z; vl[3] += blo.w;
            vh[0] += bhi.x; vh[1] += bhi.y; vh[2] += bhi.z; vh[3] += bhi.w;
            if (act) {
                #pragma unroll
                for (int j = 0; j < 4; j++) { vl[j] = silu_f(vl[j]); vh[j] = silu_f(vh[j]); }
            }
            const long off = (long)m * ldo;
            if (accum) {
                float4 o0 = *(const float4*)&Out[off + nlo];
                float4 o1 = *(const float4*)&Out[off + nhi];
                vl[0] += o0.x; vl[1] += o0.y; vl[2] += o0.z; vl[3] += o0.w;
                vh[0] += o1.x; vh[1] += o1.y; vh[2] += o1.z; vh[3] += o1.w;
            }
            *(float4*)&Out[off + nlo] = make_float4(vl[0], vl[1], vl[2], vl[3]);
            *(float4*)&Out[off + nhi] = make_float4(vh[0], vh[1], vh[2], vh[3]);
        }
    }
}

// ---------------- edge combine: silu(A[src]+B[dst]+C[e]) scatter into P -----
__global__ void edge_combine_kernel() {
    long idx = (long)blockIdx.x * blockDim.x + threadIdx.x;  // E * 64 items
    if (idx >= (long)N_EDGES * 64) return;
    int e  = (int)(idx >> 6);
    int j  = ((int)idx & 63) << 2;
    int s  = g_src[e];
    int d  = g_dst[e];
    float4 a = *(const float4*)&g_AB[(long)s * 512 + j];
    float4 b = *(const float4*)&g_AB[(long)d * 512 + 256 + j];
    float4 c = *(const float4*)&g_C[(long)e * 256 + j];
    float r0 = silu_f(a.x + b.x + c.x);
    float r1 = silu_f(a.y + b.y + c.y);
    float r2 = silu_f(a.z + b.z + c.z);
    float r3 = silu_f(a.w + b.w + c.w);
    float* p = &g_P[(long)d * 256 + j];
    asm volatile("red.global.add.v4.f32 [%0], {%1,%2,%3,%4};"
                 :: "l"(p), "f"(r0), "f"(r1), "f"(r2), "f"(r3) : "memory");
}

// ---------------- launch ------------------------------------------------------
extern "C" void kernel_launch(void* const* d_in, const int* in_sizes, int n_in,
                              void* d_out, int out_size) {
    const float* node_state = (const float*)d_in[0];
    const float* edge_attr  = (const float*)d_in[1];
    const float* nn_g = (const float*)d_in[2];
    const float* nn_b = (const float*)d_in[3];
    const float* mn_g = (const float*)d_in[4];
    const float* mn_b = (const float*)d_in[5];
    const float* eW1  = (const float*)d_in[6];
    const float* eb1  = (const float*)d_in[7];
    const float* eW2  = (const float*)d_in[8];
    const float* eb2  = (const float*)d_in[9];
    const float* nW1  = (const float*)d_in[10];
    const float* nb1  = (const float*)d_in[11];
    const float* nW2  = (const float*)d_in[12];
    const float* nb2  = (const float*)d_in[13];
    const void*  eidx = d_in[14];
    float* h = (float*)d_out;

    void *pY, *pAB, *pC, *pP, *pG, *pT, *pdeg;
    cudaGetSymbolAddress(&pY,  g_Y);
    cudaGetSymbolAddress(&pAB, g_AB);
    cudaGetSymbolAddress(&pC,  g_C);
    cudaGetSymbolAddress(&pP,  g_P);
    cudaGetSymbolAddress(&pG,  g_G);
    cudaGetSymbolAddress(&pT,  g_T);
    cudaGetSymbolAddress(&pdeg, g_deg);

    float* fY  = (float*)pY;
    float* fAB = (float*)pAB;
    float* fC  = (float*)pC;
    float* fP  = (float*)pP;
    float* fG  = (float*)pG;
    float* fT  = (float*)pT;
    float* fdeg = (float*)pdeg;

    cudaMemcpyAsync(h, node_state, (size_t)N_NODES * HDIM * sizeof(float),
                    cudaMemcpyDeviceToDevice, 0);
    cudaMemsetAsync(pdeg, 0, N_NODES * sizeof(float), 0);
    detect_idx_kernel<<<1, 64>>>((const long long*)eidx);
    convert_idx_kernel<<<(N_EDGES + 255) / 256, 256>>>(eidx);

    dim3 gN256(2, (N_NODES + 127) / 128);    // 256-col node GEMMs
    dim3 gN512(4, (N_NODES + 127) / 128);    // 512-col node GEMM
    dim3 gE256(2, N_EDGES / 128);            // edge-attr GEMM

    for (int i = 0; i < S_STEPS; i++) {
        const float* eW1i = eW1 + (long)i * 576 * 256;
        // 1. hn = LN(h) -> g_Y[:, 0:256]
        ln_kernel<<<N_NODES, 256>>>(h, 256, nn_g + i * HDIM, nn_b + i * HDIM,
                                    nullptr, nullptr, fY, 512);
        // 2. A = hn @ W1a ; B = hn @ W1b
        sgemm2_kernel<<<gN256, 256>>>(fY, 512, eW1i, 256, nullptr,
                                      fAB, 512, N_NODES, 256, 0, 0);
        sgemm2_kernel<<<gN256, 256>>>(fY, 512, eW1i + 256 * 256, 256, nullptr,
                                      fAB + 256, 512, N_NODES, 256, 0, 0);
        // 3. C = ea @ W1c + eb1
        sgemm2_kernel<<<gE256, 256>>>(edge_attr, 64, eW1i + 512 * 256, 256,
                                      eb1 + i * HDIM, fC, 256,
                                      N_EDGES, 64, 0, 0);
        // 4. P = segsum_dst( silu(A[src]+B[dst]+C) )
        cudaMemsetAsync(pP, 0, (size_t)N_NODES * 256 * sizeof(float), 0);
        edge_combine_kernel<<<(N_EDGES * 64) / 256, 256>>>();
        // 5. G = P @ eW2
        sgemm2_kernel<<<gN256, 256>>>(fP, 256, eW2 + (long)i * 256 * 256, 256,
                                      nullptr, fG, 256, N_NODES, 256, 0, 0);
        // 6. agg = LN(G/deg + eb2) -> g_Y[:,256:512]
        ln_kernel<<<N_NODES, 256>>>(fG, 256, mn_g + i * HDIM, mn_b + i * HDIM,
                                    eb2 + i * HDIM, fdeg, fY + 256, 512);
        // 7. T = silu(y @ nW1 + nb1)
        sgemm2_kernel<<<gN512, 256>>>(fY, 512, nW1 + (long)i * 512 * 512, 512,
                                      nb1 + i * 512, fT, 512,
                                      N_NODES, 512, 1, 0);
        // 8. h += T @ nW2 + nb2
        sgemm2_kernel<<<gN256, 256>>>(fT, 512, nW2 + (long)i * 512 * 256, 256,
                                      nb2 + i * HDIM, h, 256,
                                      N_NODES, 512, 0, 1);
    }
}

// round 4
// speedup vs baseline: 2.0813x; 1.6305x over previous
#include <cuda_runtime.h>
#include <cuda_bf16.h>
#include <math.h>
#include <stdint.h>

#define N_NODES 20000
#define NPAD    20096            // 157 * 128
#define N_EDGES 320000
#define HDIM    256
#define S_STEPS 4

typedef __nv_bfloat16 bf16;

// ---------------- device-global scratch (module-load allocated) -------------
__device__ bf16  g_Yh [NPAD * 512];      // [hn | agg] hi
__device__ bf16  g_Yl [NPAD * 512];      // [hn | agg] lo
__device__ float g_AB [NPAD * 512];      // [A | B] per node (fp32)
__device__ float g_C  [(size_t)N_EDGES * 256];  // ea@W1c + b1 per edge
__device__ float g_P  [NPAD * 256];      // segsum(silu(hidden))
__device__ bf16  g_Ph [NPAD * 256];
__device__ bf16  g_Pl [NPAD * 256];
__device__ float g_G  [NPAD * 256];      // P @ eW2
__device__ bf16  g_Th [NPAD * 512];      // silu(y@nW1+nb1) hi
__device__ bf16  g_Tl [NPAD * 512];
__device__ bf16  g_eah[(size_t)N_EDGES * 64];
__device__ bf16  g_eal[(size_t)N_EDGES * 64];
// transposed split weights, per step ([N,K] row-major)
__device__ bf16  g_W1h[4 * 512 * 256], g_W1l[4 * 512 * 256];
__device__ bf16  g_Wch[4 * 256 * 64],  g_Wcl[4 * 256 * 64];
__device__ bf16  g_W2h[4 * 256 * 256], g_W2l[4 * 256 * 256];
__device__ bf16  g_N1h[4 * 512 * 512], g_N1l[4 * 512 * 512];
__device__ bf16  g_N2h[4 * 256 * 512], g_N2l[4 * 256 * 512];
__device__ float g_deg[N_NODES];
__device__ int   g_src[N_EDGES];
__device__ int   g_dst[N_EDGES];
__device__ int   g_is64;

__device__ __forceinline__ float silu_f(float v) {
    return __fdividef(v, 1.0f + __expf(-v));
}

__device__ __forceinline__ uint32_t smem_u32(const void* p) {
    uint32_t a;
    asm("{ .reg .u64 t; cvta.to.shared.u64 t, %1; cvt.u32.u64 %0, t; }"
        : "=r"(a) : "l"(p));
    return a;
}

// ====================== small elementwise kernels ============================
__global__ void detect_idx_kernel(const long long* __restrict__ p) {
    __shared__ int bad;
    if (threadIdx.x == 0) bad = 0;
    __syncthreads();
    long long v = p[threadIdx.x];
    if (v < 0 || v >= N_NODES) bad = 1;
    __syncthreads();
    if (threadIdx.x == 0) g_is64 = bad ? 0 : 1;
}

__global__ void convert_idx_kernel(const void* __restrict__ ei) {
    int e = blockIdx.x * blockDim.x + threadIdx.x;
    if (e >= N_EDGES) return;
    int s, d;
    if (g_is64) {
        const long long* p = (const long long*)ei;
        s = (int)p[e]; d = (int)p[N_EDGES + e];
    } else {
        const int* p = (const int*)ei;
        s = p[e]; d = p[N_EDGES + e];
    }
    g_src[e] = s; g_dst[e] = d;
    atomicAdd(&g_deg[d], 1.0f);
}

__global__ void split_kernel(const float* __restrict__ in,
                             bf16* __restrict__ oh, bf16* __restrict__ ol, long n) {
    long i = (long)blockIdx.x * blockDim.x + threadIdx.x;
    if (i >= n) return;
    float v = in[i];
    bf16 h = __float2bfloat16(v);
    bf16 l = __float2bfloat16(v - __bfloat162float(h));
    oh[i] = h; ol[i] = l;
}

// transpose + split: W [K,N] fp32 row-major -> out [N,K] hi/lo bf16
__global__ void tsplit_kernel(const float* __restrict__ W, int K, int N,
                              bf16* __restrict__ oh, bf16* __restrict__ ol) {
    __shared__ float tile[32][33];
    int k0 = blockIdx.y * 32, n0 = blockIdx.x * 32;
    int tx = threadIdx.x, ty = threadIdx.y;    // 32 x 8
    #pragma unroll
    for (int i = 0; i < 32; i += 8) {
        int k = k0 + ty + i, n = n0 + tx;
        tile[ty + i][tx] = (k < K && n < N) ? W[(long)k * N + n] : 0.0f;
    }
    __syncthreads();
    #pragma unroll
    for (int i = 0; i < 32; i += 8) {
        int n = n0 + ty + i, k = k0 + tx;
        if (n < N && k < K) {
            float v = tile[tx][ty + i];
            bf16 h = __float2bfloat16(v);
            bf16 l = __float2bfloat16(v - __bfloat162float(h));
            oh[(long)n * K + k] = h;
            ol[(long)n * K + k] = l;
        }
    }
}

// ---------------- layer norm -> split bf16 output ----------------------------
__global__ void ln_kernel(const float* __restrict__ x, long ldx,
                          const float* __restrict__ gamma,
                          const float* __restrict__ beta,
                          const float* __restrict__ preBias,
                          const float* __restrict__ deg,
                          bf16* __restrict__ outH, bf16* __restrict__ outL,
                          long ldo, int colOff) {
    int n = blockIdx.x, t = threadIdx.x;
    float v = x[(long)n * ldx + t];
    if (deg) v = v / fmaxf(deg[n], 1.0f) + preBias[t];
    float s = v, s2 = v * v;
    #pragma unroll
    for (int o = 16; o; o >>= 1) {
        s  += __shfl_xor_sync(0xFFFFFFFFu, s,  o);
        s2 += __shfl_xor_sync(0xFFFFFFFFu, s2, o);
    }
    __shared__ float as[8], as2[8];
    int w = t >> 5, l = t & 31;
    if (l == 0) { as[w] = s; as2[w] = s2; }
    __syncthreads();
    float S = 0.f, S2 = 0.f;
    #pragma unroll
    for (int i = 0; i < 8; i++) { S += as[i]; S2 += as2[i]; }
    float mean = S * (1.0f / 256.0f);
    float var  = S2 * (1.0f / 256.0f) - mean * mean;
    float rstd = rsqrtf(var + 1e-5f);
    float r = (v - mean) * rstd * gamma[t] + beta[t];
    bf16 h = __float2bfloat16(r);
    bf16 lo = __float2bfloat16(r - __bfloat162float(h));
    long off = (long)n * ldo + colOff + t;
    outH[off] = h; outL[off] = lo;
}

// ============== HMMA split-bf16 GEMM: Out = op(A@B^T + bias) =================
// BM=128, BN=128, BK=32, 256 threads (8 warps = 2Mx4N, warp tile 64x32).
// A hi/lo bf16 [M,K] (lda), B hi/lo bf16 [N,K] (ldb). 3-term split:
// D = Ah Bh + Al Bh + Ah Bl.  K % 32 == 0. A-side rows must be readable up to
// 128-multiple (scratch is padded & zeroed); stores guarded by m < M.
#define PITCH 80                 // bytes per 32-bf16 row (conflict-free ldmatrix)
#define S_AH 0
#define S_AL 10240
#define S_BH 20480
#define S_BL 30720
#define STAGE 40960
#define GEMM_SMEM (2 * STAGE)

#define LDSM4(R, ADDR) \
    asm volatile("ldmatrix.sync.aligned.m8n8.x4.shared.b16 {%0,%1,%2,%3}, [%4];" \
                 : "=r"((R)[0]), "=r"((R)[1]), "=r"((R)[2]), "=r"((R)[3]) : "r"(ADDR))

#define MMA16816(C, A, B0, B1) \
    asm volatile("mma.sync.aligned.m16n8k16.row.col.f32.bf16.bf16.f32 " \
                 "{%0,%1,%2,%3}, {%4,%5,%6,%7}, {%8,%9}, {%0,%1,%2,%3};" \
                 : "+f"((C)[0]), "+f"((C)[1]), "+f"((C)[2]), "+f"((C)[3]) \
                 : "r"((A)[0]), "r"((A)[1]), "r"((A)[2]), "r"((A)[3]), \
                   "r"(B0), "r"(B1))

#define CP16(DST, SRC) \
    asm volatile("cp.async.cg.shared.global [%0], [%1], 16;" :: "r"(DST), "l"(SRC))

__global__ void __launch_bounds__(256, 1)
mma_gemm(const bf16* __restrict__ Ah, const bf16* __restrict__ Al, long lda,
         const bf16* __restrict__ Bh, const bf16* __restrict__ Bl, long ldb,
         const float* __restrict__ bias,
         float* __restrict__ Out, bf16* __restrict__ OutH, bf16* __restrict__ OutL,
         long ldo, int M, int K, int act, int accum) {
    extern __shared__ char smem[];
    const uint32_t sb = smem_u32(smem);
    const int tid  = threadIdx.x;
    const int lane = tid & 31;
    const int wid  = tid >> 5;
    const long bm = (long)blockIdx.y * 128;
    const long bn = (long)blockIdx.x * 128;
    const int wm = (wid & 1) * 64;       // warp M offset
    const int wn = (wid >> 1) * 32;      // warp N offset

    float acc[4][4][4];
    #pragma unroll
    for (int i = 0; i < 4; i++)
        #pragma unroll
        for (int j = 0; j < 4; j++)
            #pragma unroll
            for (int q = 0; q < 4; q++) acc[i][j][q] = 0.0f;

    const int nk = K >> 5;

    // loader: 8 x 16B per thread per stage (2048 chunks total)
    const int lrow0 = tid >> 2;          // 0..63 (+64 for odd sub-iter)
    const int lkc   = tid & 3;           // 16B chunk within 32-bf16 row

    // issue cp.async for stage kt
    #define ISSUE(kt) do {                                                     \
        const uint32_t st = sb + ((kt) & 1) * STAGE;                           \
        const long k0 = (long)(kt) << 5;                                       \
        _Pragma("unroll")                                                      \
        for (int i = 0; i < 8; i++) {                                          \
            const int part = i >> 1;                                           \
            const int row = lrow0 + (i & 1) * 64;                              \
            const uint32_t d = st + part * 10240 + row * PITCH + lkc * 16;     \
            const bf16* g;                                                     \
            if (part == 0)      g = Ah + (bm + row) * lda + k0 + lkc * 8;      \
            else if (part == 1) g = Al + (bm + row) * lda + k0 + lkc * 8;      \
            else if (part == 2) g = Bh + (bn + row) * ldb + k0 + lkc * 8;      \
            else                g = Bl + (bn + row) * ldb + k0 + lkc * 8;      \
            CP16(d, g);                                                        \
        }                                                                      \
        asm volatile("cp.async.commit_group;");                                \
    } while (0)

    ISSUE(0);

    // ldmatrix base offsets (per warp, per lane)
    const uint32_t a_off = (uint32_t)((wm + (lane & 15)) * PITCH + (lane >> 4) * 16);
    const uint32_t b_off = (uint32_t)((wn + (lane & 15)) * PITCH + (lane >> 4) * 16);

    for (int kt = 0; kt < nk; kt++) {
        if (kt + 1 < nk) {
            ISSUE(kt + 1);
            asm volatile("cp.async.wait_group 1;");
        } else {
            asm volatile("cp.async.wait_group 0;");
        }
        __syncthreads();
        const uint32_t st = sb + (kt & 1) * STAGE;
        #pragma unroll
        for (int h = 0; h < 2; h++) {
            uint32_t ah[4][4], al[4][4];
            #pragma unroll
            for (int mi = 0; mi < 4; mi++) {
                LDSM4(ah[mi], st + S_AH + a_off + mi * (16 * PITCH) + h * 32);
                LDSM4(al[mi], st + S_AL + a_off + mi * (16 * PITCH) + h * 32);
            }
            uint32_t bh[2][4], bl[2][4];
            #pragma unroll
            for (int jj = 0; jj < 2; jj++) {
                LDSM4(bh[jj], st + S_BH + b_off + jj * (16 * PITCH) + h * 32);
                LDSM4(bl[jj], st + S_BL + b_off + jj * (16 * PITCH) + h * 32);
            }
            #pragma unroll
            for (int mi = 0; mi < 4; mi++)
                #pragma unroll
                for (int j = 0; j < 4; j++) {
                    const int jj = j >> 1, jo = j & 1;
                    MMA16816(acc[mi][j], ah[mi], bh[jj][jo], bh[jj][2 + jo]);
                    MMA16816(acc[mi][j], al[mi], bh[jj][jo], bh[jj][2 + jo]);
                    MMA16816(acc[mi][j], ah[mi], bl[jj][jo], bl[jj][2 + jo]);
                }
        }
        __syncthreads();
    }

    // ---------------- epilogue ----------------
    const int r0 = lane >> 2;            // 0..7
    const int c0 = (lane & 3) * 2;       // 0,2,4,6
    float2 bv[4];
    if (bias) {
        #pragma unroll
        for (int j = 0; j < 4; j++)
            bv[j] = *(const float2*)&bias[bn + wn + j * 8 + c0];
    } else {
        #pragma unroll
        for (int j = 0; j < 4; j++) bv[j] = make_float2(0.f, 0.f);
    }
    #pragma unroll
    for (int mi = 0; mi < 4; mi++) {
        #pragma unroll
        for (int half = 0; half < 2; half++) {
            const long m = bm + wm + mi * 16 + r0 + half * 8;
            if (m >= M) continue;
            #pragma unroll
            for (int j = 0; j < 4; j++) {
                float x = acc[mi][j][half * 2 + 0] + bv[j].x;
                float y = acc[mi][j][half * 2 + 1] + bv[j].y;
                if (act) { x = silu_f(x); y = silu_f(y); }
                const long col = bn + wn + j * 8 + c0;
                if (OutH) {
                    bf16 hx = __float2bfloat16(x), hy = __float2bfloat16(y);
                    bf16 lx = __float2bfloat16(x - __bfloat162float(hx));
                    bf16 ly = __float2bfloat16(y - __bfloat162float(hy));
                    uint32_t hw = ((uint32_t)__bfloat16_as_ushort(hy) << 16) |
                                  __bfloat16_as_ushort(hx);
                    uint32_t lw = ((uint32_t)__bfloat16_as_ushort(ly) << 16) |
                                  __bfloat16_as_ushort(lx);
                    *(uint32_t*)(OutH + m * ldo + col) = hw;
                    *(uint32_t*)(OutL + m * ldo + col) = lw;
                } else {
                    float* o = Out + m * ldo + col;
                    if (accum) {
                        float2 old = *(const float2*)o;
                        x += old.x; y += old.y;
                    }
                    *(float2*)o = make_float2(x, y);
                }
            }
        }
    }
}

// ---------------- edge combine: silu(A[src]+B[dst]+C[e]) scatter into P -----
__global__ void edge_combine_kernel() {
    long idx = (long)blockIdx.x * blockDim.x + threadIdx.x;
    if (idx >= (long)N_EDGES * 64) return;
    int e = (int)(idx >> 6);
    int j = ((int)idx & 63) << 2;
    int s = g_src[e];
    int d = g_dst[e];
    float4 a = *(const float4*)&g_AB[(long)s * 512 + j];
    float4 b = *(const float4*)&g_AB[(long)d * 512 + 256 + j];
    float4 c = *(const float4*)&g_C[(long)e * 256 + j];
    float r0 = silu_f(a.x + b.x + c.x);
    float r1 = silu_f(a.y + b.y + c.y);
    float r2 = silu_f(a.z + b.z + c.z);
    float r3 = silu_f(a.w + b.w + c.w);
    float* p = &g_P[(long)d * 256 + j];
    asm volatile("red.global.add.v4.f32 [%0], {%1,%2,%3,%4};"
                 :: "l"(p), "f"(r0), "f"(r1), "f"(r2), "f"(r3) : "memory");
}

// ============================ launch =========================================
extern "C" void kernel_launch(void* const* d_in, const int* in_sizes, int n_in,
                              void* d_out, int out_size) {
    const float* node_state = (const float*)d_in[0];
    const float* edge_attr  = (const float*)d_in[1];
    const float* nn_g = (const float*)d_in[2];
    const float* nn_b = (const float*)d_in[3];
    const float* mn_g = (const float*)d_in[4];
    const float* mn_b = (const float*)d_in[5];
    const float* eW1  = (const float*)d_in[6];
    const float* eb1  = (const float*)d_in[7];
    const float* eW2  = (const float*)d_in[8];
    const float* eb2  = (const float*)d_in[9];
    const float* nW1  = (const float*)d_in[10];
    const float* nb1  = (const float*)d_in[11];
    const float* nW2  = (const float*)d_in[12];
    const float* nb2  = (const float*)d_in[13];
    const void*  eidx = d_in[14];
    float* h = (float*)d_out;

    cudaFuncSetAttribute(mma_gemm, cudaFuncAttributeMaxDynamicSharedMemorySize,
                         GEMM_SMEM);

    void *pYh, *pYl, *pAB, *pC, *pP, *pPh, *pPl, *pG, *pTh, *pTl,
         *pEah, *pEal, *pW1h, *pW1l, *pWch, *pWcl, *pW2h, *pW2l,
         *pN1h, *pN1l, *pN2h, *pN2l, *pdeg;
    cudaGetSymbolAddress(&pYh, g_Yh);   cudaGetSymbolAddress(&pYl, g_Yl);
    cudaGetSymbolAddress(&pAB, g_AB);   cudaGetSymbolAddress(&pC, g_C);
    cudaGetSymbolAddress(&pP, g_P);     cudaGetSymbolAddress(&pPh, g_Ph);
    cudaGetSymbolAddress(&pPl, g_Pl);   cudaGetSymbolAddress(&pG, g_G);
    cudaGetSymbolAddress(&pTh, g_Th);   cudaGetSymbolAddress(&pTl, g_Tl);
    cudaGetSymbolAddress(&pEah, g_eah); cudaGetSymbolAddress(&pEal, g_eal);
    cudaGetSymbolAddress(&pW1h, g_W1h); cudaGetSymbolAddress(&pW1l, g_W1l);
    cudaGetSymbolAddress(&pWch, g_Wch); cudaGetSymbolAddress(&pWcl, g_Wcl);
    cudaGetSymbolAddress(&pW2h, g_W2h); cudaGetSymbolAddress(&pW2l, g_W2l);
    cudaGetSymbolAddress(&pN1h, g_N1h); cudaGetSymbolAddress(&pN1l, g_N1l);
    cudaGetSymbolAddress(&pN2h, g_N2h); cudaGetSymbolAddress(&pN2l, g_N2l);
    cudaGetSymbolAddress(&pdeg, g_deg);

    bf16 *Yh=(bf16*)pYh, *Yl=(bf16*)pYl, *Ph=(bf16*)pPh, *Pl=(bf16*)pPl,
         *Th=(bf16*)pTh, *Tl=(bf16*)pTl, *Eah=(bf16*)pEah, *Eal=(bf16*)pEal,
         *W1h=(bf16*)pW1h, *W1l=(bf16*)pW1l, *Wch=(bf16*)pWch, *Wcl=(bf16*)pWcl,
         *W2h=(bf16*)pW2h, *W2l=(bf16*)pW2l, *N1h=(bf16*)pN1h, *N1l=(bf16*)pN1l,
         *N2h=(bf16*)pN2h, *N2l=(bf16*)pN2l;
    float *AB=(float*)pAB, *C=(float*)pC, *P=(float*)pP, *G=(float*)pG,
          *deg=(float*)pdeg;

    // ---- one-time prep ----
    cudaMemcpyAsync(h, node_state, (size_t)N_NODES * HDIM * sizeof(float),
                    cudaMemcpyDeviceToDevice, 0);
    cudaMemsetAsync(pdeg, 0, N_NODES * sizeof(float), 0);
    detect_idx_kernel<<<1, 64>>>((const long long*)eidx);
    convert_idx_kernel<<<(N_EDGES + 255) / 256, 256>>>(eidx);
    split_kernel<<<((long)N_EDGES * 64 + 255) / 256, 256>>>(edge_attr, Eah, Eal,
                                                            (long)N_EDGES * 64);
    dim3 tb(32, 8);
    for (int i = 0; i < S_STEPS; i++) {
        const float* W1 = eW1 + (long)i * 576 * 256;
        tsplit_kernel<<<dim3(8, 8), tb>>>(W1, 256, 256,
                                          W1h + (long)i * 512 * 256,
                                          W1l + (long)i * 512 * 256);
        tsplit_kernel<<<dim3(8, 8), tb>>>(W1 + 256 * 256, 256, 256,
                                          W1h + (long)i * 512 * 256 + 256 * 256,
                                          W1l + (long)i * 512 * 256 + 256 * 256);
        tsplit_kernel<<<dim3(8, 2), tb>>>(W1 + 512 * 256, 64, 256,
                                          Wch + (long)i * 256 * 64,
                                          Wcl + (long)i * 256 * 64);
        tsplit_kernel<<<dim3(8, 8), tb>>>(eW2 + (long)i * 256 * 256, 256, 256,
                                          W2h + (long)i * 256 * 256,
                                          W2l + (long)i * 256 * 256);
        tsplit_kernel<<<dim3(16, 16), tb>>>(nW1 + (long)i * 512 * 512, 512, 512,
                                            N1h + (long)i * 512 * 512,
                                            N1l + (long)i * 512 * 512);
        tsplit_kernel<<<dim3(8, 16), tb>>>(nW2 + (long)i * 512 * 256, 512, 256,
                                           N2h + (long)i * 256 * 512,
                                           N2l + (long)i * 256 * 512);
    }

    const int MT = NPAD / 128;     // 157 M-tiles (node GEMMs)
    const int ET = N_EDGES / 128;  // 2500 M-tiles (edge GEMM)

    for (int i = 0; i < S_STEPS; i++) {
        // 1. hn = LN(h) -> Y[:, 0:256]
        ln_kernel<<<N_NODES, 256>>>(h, 256, nn_g + i * HDIM, nn_b + i * HDIM,
                                    nullptr, nullptr, Yh, Yl, 512, 0);
        // 2. AB = hn @ [W1a|W1b]   (M=20000, K=256, N=512)
        mma_gemm<<<dim3(4, MT), 256, GEMM_SMEM>>>(
            Yh, Yl, 512, W1h + (long)i * 512 * 256, W1l + (long)i * 512 * 256, 256,
            nullptr, AB, nullptr, nullptr, 512, N_NODES, 256, 0, 0);
        // 3. C = ea @ W1c + eb1    (M=320000, K=64, N=256)
        mma_gemm<<<dim3(2, ET), 256, GEMM_SMEM>>>(
            Eah, Eal, 64, Wch + (long)i * 256 * 64, Wcl + (long)i * 256 * 64, 64,
            eb1 + i * HDIM, C, nullptr, nullptr, 256, N_EDGES, 64, 0, 0);
        // 4. P = segsum_dst(silu(A[src]+B[dst]+C))
        cudaMemsetAsync(pP, 0, (size_t)N_NODES * 256 * sizeof(float), 0);
        edge_combine_kernel<<<((long)N_EDGES * 64) / 256, 256>>>();
        split_kernel<<<((long)N_NODES * 256 + 255) / 256, 256>>>(P, Ph, Pl,
                                                                 (long)N_NODES * 256);
        // 5. G = P @ eW2           (M=20000, K=256, N=256)
        mma_gemm<<<dim3(2, MT), 256, GEMM_SMEM>>>(
            Ph, Pl, 256, W2h + (long)i * 256 * 256, W2l + (long)i * 256 * 256, 256,
            nullptr, G, nullptr, nullptr, 256, N_NODES, 256, 0, 0);
        // 6. agg = LN(G/deg + eb2) -> Y[:, 256:512]
        ln_kernel<<<N_NODES, 256>>>(G, 256, mn_g + i * HDIM, mn_b + i * HDIM,
                                    eb2 + i * HDIM, deg, Yh, Yl, 512, 256);
        // 7. T = silu(y @ nW1 + nb1)  (M=20000, K=512, N=512, split bf16 out)
        mma_gemm<<<dim3(4, MT), 256, GEMM_SMEM>>>(
            Yh, Yl, 512, N1h + (long)i * 512 * 512, N1l + (long)i * 512 * 512, 512,
            nb1 + i * 512, nullptr, Th, Tl, 512, N_NODES, 512, 1, 0);
        // 8. h += T @ nW2 + nb2    (M=20000, K=512, N=256, fp32 accum)
        mma_gemm<<<dim3(2, MT), 256, GEMM_SMEM>>>(
            Th, Tl, 512, N2h + (long)i * 256 * 512, N2l + (long)i * 256 * 512, 512,
            nb2 + i * HDIM, h, nullptr, nullptr, 256, N_NODES, 512, 0, 1);
    }
}